// round 8
// baseline (speedup 1.0000x reference)
#include <cuda_runtime.h>

#define NN 100000
#define EE 1600000
#define DD 64
#define EPS 1e-5f

#define NBLK 98                       // ceil(NN/1024)
#define NN_PAD (NBLK * 1024)          // 100352

// ---------------- device scratch (no allocations allowed) ----------------
__device__ __align__(16) int   g_deg[NN_PAD];      // edge count per target (zero-init; re-zeroed each launch)
__device__ __align__(16) float g_dinv[NN_PAD];     // rsqrt(deg+1)
__device__ __align__(16) int   g_off[NN_PAD];      // CSR offsets
__device__ __align__(16) int   g_cursor[NN_PAD];   // fill cursors
__device__                int   g_bsum[NBLK];
__device__                int   g_bpre[NBLK];
__device__ __align__(8)  int2  g_edge[EE];         // (src, float-bits weight)
__device__ __align__(16) float g_h1[NN * DD];      // ping
__device__ __align__(16) float g_h2[NN * DD];      // pong

// ---------------- CSR build ----------------
__global__ __launch_bounds__(256) void k_count(const int* __restrict__ ei) {
    int e = blockIdx.x * blockDim.x + threadIdx.x;
    if (e < EE) atomicAdd(&g_deg[ei[EE + e]], 1);
}

__global__ __launch_bounds__(256) void k_bsum() {
    const int t = threadIdx.x, b = blockIdx.x;
    const int4* d4 = (const int4*)g_deg;
    int4 v = d4[b * 256 + t];
    int s = v.x + v.y + v.z + v.w;
#pragma unroll
    for (int m = 16; m; m >>= 1) s += __shfl_xor_sync(0xffffffffu, s, m);
    __shared__ int ws[8];
    if ((t & 31) == 0) ws[t >> 5] = s;
    __syncthreads();
    if (t == 0) {
        int x = 0;
#pragma unroll
        for (int i = 0; i < 8; i++) x += ws[i];
        g_bsum[b] = x;
    }
}

__global__ __launch_bounds__(128) void k_bscan() {
    __shared__ int s[128];
    const int t = threadIdx.x;
    int v = (t < NBLK) ? g_bsum[t] : 0;
    s[t] = v;
    __syncthreads();
    for (int off = 1; off < 128; off <<= 1) {
        int u = (t >= off) ? s[t - off] : 0;
        __syncthreads();
        s[t] += u;
        __syncthreads();
    }
    if (t < NBLK) g_bpre[t] = s[t] - v;  // exclusive
}

// writes g_off, g_cursor, g_dinv; re-zeroes g_deg for the next launch
__global__ __launch_bounds__(256) void k_bscan_fill() {
    const int t = threadIdx.x, b = blockIdx.x;
    const int lane = t & 31, wid = t >> 5;
    const int4* d4 = (const int4*)g_deg;
    int4 c = d4[b * 256 + t];
    int sum4 = c.x + c.y + c.z + c.w;

    int inc = sum4;
#pragma unroll
    for (int m = 1; m < 32; m <<= 1) {
        int u = __shfl_up_sync(0xffffffffu, inc, m);
        if (lane >= m) inc += u;
    }
    __shared__ int wsum[8], wpre[8];
    if (lane == 31) wsum[wid] = inc;
    __syncthreads();
    if (t == 0) {
        int r = 0;
#pragma unroll
        for (int i = 0; i < 8; i++) { wpre[i] = r; r += wsum[i]; }
    }
    __syncthreads();

    int excl = inc - sum4 + wpre[wid] + g_bpre[b];
    int o0 = excl, o1 = o0 + c.x, o2 = o1 + c.y, o3 = o2 + c.z;
    int4 off4 = make_int4(o0, o1, o2, o3);
    ((int4*)g_off)[b * 256 + t] = off4;
    ((int4*)g_cursor)[b * 256 + t] = off4;
    float4 dv;
    dv.x = rsqrtf((float)(c.x + 1));
    dv.y = rsqrtf((float)(c.y + 1));
    dv.z = rsqrtf((float)(c.z + 1));
    dv.w = rsqrtf((float)(c.w + 1));
    ((float4*)g_dinv)[b * 256 + t] = dv;
    ((int4*)g_deg)[b * 256 + t] = make_int4(0, 0, 0, 0);  // reset for next launch
}

__global__ __launch_bounds__(256) void k_fill(const int* __restrict__ ei) {
    int e = blockIdx.x * blockDim.x + threadIdx.x;
    if (e < EE) {
        int r = ei[e];
        int c = ei[EE + e];
        int p = atomicAdd(&g_cursor[c], 1);
        float w = g_dinv[r] * g_dinv[c];
        g_edge[p] = make_int2(r, __float_as_int(w));
    }
}

// ---------------- fused layer: out = act(LN((A_hat h) W + b)) ----------------
// 512 threads = 32 node-groups of 16 lanes.
// Phase 1: gather-sum s = A_hat h  (memory-bound)
// Phase 2: per-node GEMM s@W via packed fma.f32x2 + bias + LN (+ReLU)
__global__ __launch_bounds__(512) void k_layer(const float* __restrict__ hin,
                                               const float* __restrict__ W,
                                               const float* __restrict__ bias,
                                               const float* __restrict__ gamma,
                                               const float* __restrict__ beta,
                                               float* __restrict__ out,
                                               int do_relu) {
    __shared__ float4 sW[64 * 16];   // [k][j4]
    __shared__ float  sS[32][68];    // aggregated s per node (68-pad)

    const int t = threadIdx.x;
    const float4* W4 = (const float4*)W;
#pragma unroll
    for (int i = 0; i < 2; i++) sW[t + i * 512] = W4[t + i * 512];
    __syncthreads();

    const int g = t >> 4;                      // node group 0..31
    const int j = t & 15;                      // col group (4 cols)
    const int node = blockIdx.x * 32 + g;      // NN % 32 == 0
    const unsigned gmask = 0xffffu << (t & 16);
    const float4* h4 = (const float4*)hin;

    // ---- phase 1: gather ----
    float dn = g_dinv[node];
    float4 acc = h4[node * 16 + j];
    float wself = dn * dn;
    acc.x *= wself; acc.y *= wself; acc.z *= wself; acc.w *= wself;

    int p = g_off[node];
    const int pend = g_off[node + 1];
    while (p + 16 <= pend) {
        int2 e = __ldg(&g_edge[p + j]);
#pragma unroll
        for (int i = 0; i < 16; i++) {
            int src = __shfl_sync(gmask, e.x, i, 16);
            float w = __int_as_float(__shfl_sync(gmask, e.y, i, 16));
            float4 v = h4[src * 16 + j];
            acc.x += w * v.x;
            acc.y += w * v.y;
            acc.z += w * v.z;
            acc.w += w * v.w;
        }
        p += 16;
    }
    int rem = pend - p;
    if (rem > 0) {
        int2 e = make_int2(0, 0);
        if (j < rem) e = __ldg(&g_edge[p + j]);
        for (int i = 0; i < rem; i++) {
            int src = __shfl_sync(gmask, e.x, i, 16);
            float w = __int_as_float(__shfl_sync(gmask, e.y, i, 16));
            float4 v = h4[src * 16 + j];
            acc.x += w * v.x;
            acc.y += w * v.y;
            acc.z += w * v.z;
            acc.w += w * v.w;
        }
    }

    // ---- exchange s within the half-warp group ----
    ((float4*)&sS[g][0])[j] = acc;
    __syncwarp();

    // ---- phase 2: y[j4] = sum_k s[k] * W[k][j4]  (packed f32x2 FMA) ----
    unsigned long long a01 = 0ull, a23 = 0ull;
    const float4* srow = (const float4*)&sS[g][0];
    const ulonglong2* sW2 = (const ulonglong2*)sW;
#pragma unroll
    for (int k4 = 0; k4 < 16; k4++) {
        float4 s4 = srow[k4];
        float sv[4] = {s4.x, s4.y, s4.z, s4.w};
#pragma unroll
        for (int i = 0; i < 4; i++) {
            unsigned long long hh;
            asm("mov.b64 %0, {%1, %2};" : "=l"(hh) : "f"(sv[i]), "f"(sv[i]));
            ulonglong2 w2 = sW2[(k4 * 4 + i) * 16 + j];
            asm("fma.rn.f32x2 %0, %1, %2, %3;" : "=l"(a01) : "l"(hh), "l"(w2.x), "l"(a01));
            asm("fma.rn.f32x2 %0, %1, %2, %3;" : "=l"(a23) : "l"(hh), "l"(w2.y), "l"(a23));
        }
    }
    float y0, y1, y2, y3;
    asm("mov.b64 {%0, %1}, %2;" : "=f"(y0), "=f"(y1) : "l"(a01));
    asm("mov.b64 {%0, %1}, %2;" : "=f"(y2), "=f"(y3) : "l"(a23));

    float4 b = ((const float4*)bias)[j];
    y0 += b.x; y1 += b.y; y2 += b.z; y3 += b.w;

    // ---- LayerNorm over 64 values (16 lanes x 4) ----
    float lsum = y0 + y1 + y2 + y3;
    float lsq  = y0 * y0 + y1 * y1 + y2 * y2 + y3 * y3;
#pragma unroll
    for (int m = 8; m >= 1; m >>= 1) {
        lsum += __shfl_xor_sync(gmask, lsum, m, 16);
        lsq  += __shfl_xor_sync(gmask, lsq,  m, 16);
    }
    float mean = lsum * (1.0f / 64.0f);
    float var = lsq * (1.0f / 64.0f) - mean * mean;
    float rstd = rsqrtf(var + EPS);

    float4 ga = ((const float4*)gamma)[j];
    float4 be = ((const float4*)beta)[j];
    float4 o;
    o.x = (y0 - mean) * rstd * ga.x + be.x;
    o.y = (y1 - mean) * rstd * ga.y + be.y;
    o.z = (y2 - mean) * rstd * ga.z + be.z;
    o.w = (y3 - mean) * rstd * ga.w + be.w;
    if (do_relu) {
        o.x = fmaxf(o.x, 0.f);
        o.y = fmaxf(o.y, 0.f);
        o.z = fmaxf(o.z, 0.f);
        o.w = fmaxf(o.w, 0.f);
    }
    ((float4*)out)[node * 16 + j] = o;
}

// ---------------- launch ----------------
extern "C" void kernel_launch(void* const* d_in, const int* in_sizes, int n_in,
                              void* d_out, int out_size) {
    const float* x      = (const float*)d_in[0];   // (N, D)
    const float* Ws     = (const float*)d_in[1];   // (L, D, D)
    const float* bs     = (const float*)d_in[2];   // (L, D)
    const float* gammas = (const float*)d_in[3];   // (L, D)
    const float* betas  = (const float*)d_in[4];   // (L, D)
    const int*   ei     = (const int*)d_in[5];     // (2, E)
    float* outp = (float*)d_out;

    float* d_h1;
    float* d_h2;
    cudaGetSymbolAddress((void**)&d_h1, g_h1);
    cudaGetSymbolAddress((void**)&d_h2, g_h2);

    const int TB = 256;
    const int gE = (EE + TB - 1) / TB;
    const int gLayer = NN / 32;   // 3125

    // CSR build (g_deg zeroed by previous launch / module init)
    k_count<<<gE, TB>>>(ei);
    k_bsum<<<NBLK, 256>>>();
    k_bscan<<<1, 128>>>();
    k_bscan_fill<<<NBLK, 256>>>();
    k_fill<<<gE, TB>>>(ei);

    // fused layers (launch index 5 = layer 0 -> profiled by ncu -s 5)
    k_layer<<<gLayer, 512>>>(x,    Ws + 0 * DD * DD, bs + 0 * DD, gammas + 0 * DD, betas + 0 * DD, d_h1, 1);
    k_layer<<<gLayer, 512>>>(d_h1, Ws + 1 * DD * DD, bs + 1 * DD, gammas + 1 * DD, betas + 1 * DD, d_h2, 1);
    k_layer<<<gLayer, 512>>>(d_h2, Ws + 2 * DD * DD, bs + 2 * DD, gammas + 2 * DD, betas + 2 * DD, outp, 0);
}